// round 6
// baseline (speedup 1.0000x reference)
#include <cuda_runtime.h>

// ProdAt: x [16384, 8192] fp32 -> out [16384, 128] fp32
// out[seg] = prod of 64 contiguous floats.
//
// Software-pipelined 2-chunk variant:
//   8 lanes per segment; each lane loads f4[sub] and f4[sub+8] (each LDG.128
//   by an 8-lane group covers one full 128B line -> perfect coalescing).
//   Each warp handles 16 segments as two 8-seg chunks; all 8 LDG.128 are
//   front-batched (staged MLP=8) so memory stays busy while the shfl
//   reductions of both chunks retire. Each thread owns 2 ADJACENT segments
//   per chunk; sub==0 lanes store packed float2 (STG.64).

static constexpr long long N_SEGMENTS_TOTAL = 16384LL * 128LL;  // 2,097,152

__device__ __forceinline__ float prod4(float4 v) {
    return (v.x * v.y) * (v.z * v.w);
}

__global__ void __launch_bounds__(512) prodat_kernel(
    const float* __restrict__ x, float* __restrict__ out)
{
    const long long warp_id =
        (long long)blockIdx.x * (blockDim.x >> 5) + (threadIdx.x >> 5);
    const int lane = threadIdx.x & 31;

    const int g   = lane >> 3;   // 0..3 : segment-pair group within warp
    const int sub = lane & 7;    // 0..7 : float4 slot within segment half

    // warp covers 16 consecutive segments [warp_id*16, warp_id*16+16)
    const long long s00 = warp_id * 16 + 2 * g;      // chunk0: segs s00, s00+1
    const long long s01 = s00 + 1;
    const long long s10 = s00 + 8;                   // chunk1: segs s10, s10+1
    const long long s11 = s10 + 1;

    const float4* x4 = reinterpret_cast<const float4*>(x);

    // front-batch all 8 independent loads (staged MLP = 8)
    const float4 a0 = __ldcs(x4 + s00 * 16 + sub);
    const float4 b0 = __ldcs(x4 + s00 * 16 + 8 + sub);
    const float4 a1 = __ldcs(x4 + s01 * 16 + sub);
    const float4 b1 = __ldcs(x4 + s01 * 16 + 8 + sub);
    const float4 a2 = __ldcs(x4 + s10 * 16 + sub);
    const float4 b2 = __ldcs(x4 + s10 * 16 + 8 + sub);
    const float4 a3 = __ldcs(x4 + s11 * 16 + sub);
    const float4 b3 = __ldcs(x4 + s11 * 16 + 8 + sub);

    float p0 = prod4(a0) * prod4(b0);
    float p1 = prod4(a1) * prod4(b1);
    float p2 = prod4(a2) * prod4(b2);
    float p3 = prod4(a3) * prod4(b3);

    // four independent 3-step reductions over the 8-lane group (pipelined)
    #pragma unroll
    for (int off = 4; off > 0; off >>= 1) {
        p0 *= __shfl_xor_sync(0xffffffffu, p0, off);
        p1 *= __shfl_xor_sync(0xffffffffu, p1, off);
        p2 *= __shfl_xor_sync(0xffffffffu, p2, off);
        p3 *= __shfl_xor_sync(0xffffffffu, p3, off);
    }

    if (sub == 0) {
        float2* out2 = reinterpret_cast<float2*>(out);
        out2[s00 >> 1] = make_float2(p0, p1);   // STG.64
        out2[s10 >> 1] = make_float2(p2, p3);   // STG.64
    }
}

extern "C" void kernel_launch(void* const* d_in, const int* in_sizes, int n_in,
                              void* d_out, int out_size)
{
    const float* x = (const float*)d_in[0];
    float* out = (float*)d_out;

    // 512 threads = 16 warps = 256 segments per block
    const int threads = 512;
    const long long blocks = N_SEGMENTS_TOTAL / 256;  // 8192, exact

    prodat_kernel<<<(unsigned)blocks, threads>>>(x, out);
}